// round 9
// baseline (speedup 1.0000x reference)
#include <cuda_runtime.h>

#define BB 4
#define NB 8
#define HH 512
#define WW 512
#define HWs (HH*WW)
#define KS 41
#define KR 20
#define SS 128
#define EPSF 1e-20f
#define BETAD 0.25

// ---------------- device scratch ----------------
__device__ float g_v[NB*KS];
__device__ float g_sp[BB*NB*HH*SS];
__device__ float g_panf[BB*HWs];
__device__ float g_dapf[BB*HWs];
__device__ float g_saapf[BB*HWs];
__device__ float g_dbpan[BB*HWs];
__device__ float g_sbbpan[BB*HWs];
__device__ double g_acc[3];

// ---------------- reduction helpers ----------------
__device__ __forceinline__ void block_reduce2(float a, float b, double* d0, double* d1) {
    #pragma unroll
    for (int o = 16; o; o >>= 1) {
        a += __shfl_down_sync(0xffffffffu, a, o);
        b += __shfl_down_sync(0xffffffffu, b, o);
    }
    __shared__ float sa[8], sb[8];
    int lane = threadIdx.x & 31, wid = threadIdx.x >> 5;
    if (lane == 0) { sa[wid] = a; sb[wid] = b; }
    __syncthreads();
    if (wid == 0) {
        int nw = blockDim.x >> 5;
        a = (lane < nw) ? sa[lane] : 0.f;
        b = (lane < nw) ? sb[lane] : 0.f;
        #pragma unroll
        for (int o = 4; o; o >>= 1) {
            a += __shfl_down_sync(0xffffffffu, a, o);
            b += __shfl_down_sync(0xffffffffu, b, o);
        }
        if (lane == 0) { atomicAdd(d0, (double)a); atomicAdd(d1, (double)b); }
    }
}

__device__ __forceinline__ void block_reduce1(float a, double* d0) {
    #pragma unroll
    for (int o = 16; o; o >>= 1) a += __shfl_down_sync(0xffffffffu, a, o);
    __shared__ float sa[8];
    int lane = threadIdx.x & 31, wid = threadIdx.x >> 5;
    if (lane == 0) sa[wid] = a;
    __syncthreads();
    if (wid == 0) {
        int nw = blockDim.x >> 5;
        a = (lane < nw) ? sa[lane] : 0.f;
        #pragma unroll
        for (int o = 4; o; o >>= 1) a += __shfl_down_sync(0xffffffffu, a, o);
        if (lane == 0) atomicAdd(d0, (double)a);
    }
}

// ---------------- setup ----------------
__global__ void k_setup(const float* __restrict__ mtf) {
    int t = blockIdx.x * blockDim.x + threadIdx.x;
    if (t < NB * KS) {
        int k = t / KS, i = t - k * KS;
        g_v[t] = mtf[k * KS * KS + i * KS + KR] / sqrtf(mtf[k * KS * KS + KR * KS + KR]);
    }
    if (t < 3) g_acc[t] = 0.0;
}

// ---------------- L_spec horizontal conv: float4 rolling window ----------------
__global__ void __launch_bounds__(256) k_spec_h(const float* __restrict__ outp) {
    int hp = blockIdx.x & 255;
    int bk = blockIdx.x >> 8;
    int k  = bk & 7;
    __shared__ __align__(16) float s_row[2][556];
    __shared__ float s_v[44];
    int t = threadIdx.x;
    if (t < 44) s_v[t] = (t < KS) ? g_v[k * KS + t] : 0.f;
    if (t < 88) { int r = t / 44, p = t % 44; s_row[r][p < 22 ? p : p - 22 + 534] = 0.f; }
    const float* src = outp + (long)bk * HWs + (long)(2 * hp) * WW;
    for (int i = t; i < 1024; i += 256) {
        int r = i >> 9, c = i & 511;
        s_row[r][22 + c] = src[r * WW + c];
    }
    __syncthreads();
    int r = t >> 7, jj = t & 127;
    const float4* row4 = reinterpret_cast<const float4*>(s_row[r]) + (jj + 1);
    float4 cur = row4[0];
    float s = 0.f;
    #pragma unroll
    for (int tt = 0; tt < 10; ++tt) {
        float4 nxt = row4[tt + 1];
        s += s_v[4*tt] * cur.x + s_v[4*tt+1] * cur.y + s_v[4*tt+2] * cur.z + s_v[4*tt+3] * cur.w;
        cur = nxt;
    }
    s += s_v[40] * cur.x;
    g_sp[((long)bk * HH + 2 * hp + r) * SS + jj] = s;
}

// ---------------- L_spec vertical: smem tile, 4 outputs/thread ----------------
__global__ void __launch_bounds__(256) k_spec_v(const float* __restrict__ labels, const float* __restrict__ mask) {
    int bk = blockIdx.y;
    int kb = bk & 7, b = bk >> 3;
    int ii0 = blockIdx.x * 8;
    __shared__ float s_sp[69][128];
    __shared__ float s_v[KS];
    int t = threadIdx.x;
    if (t < KS) s_v[t] = g_v[kb * KS + t];
    const float* spb = g_sp + (long)bk * HH * SS;
    for (int i = t; i < 69 * 128; i += 256) {
        int m = i >> 7, jj = i & 127;
        int gr = 4 * ii0 - 18 + m;
        s_sp[m][jj] = ((unsigned)gr < 512u) ? spb[(long)gr * SS + jj] : 0.f;
    }
    __syncthreads();
    int jj = t & 127, half = t >> 7;
    int base = 16 * half;
    float o0 = 0.f, o1 = 0.f, o2 = 0.f, o3 = 0.f;
    #pragma unroll
    for (int m = 0; m < 53; ++m) {
        float x = s_sp[base + m][jj];
        if (m <= 40) o0 += s_v[m] * x;
        if (m >= 4 && m <= 44) o1 += s_v[m - 4] * x;
        if (m >= 8 && m <= 48) o2 += s_v[m - 8] * x;
        if (m >= 12) o3 += s_v[m - 12] * x;
    }
    float xs[4] = {o0, o1, o2, o3};
    float num = 0.f, den = 0.f;
    #pragma unroll
    for (int q = 0; q < 4; ++q) {
        int ii = ii0 + 4 * half + q;
        int row = 2 + 4 * ii, col = 2 + 4 * jj;
        float y = labels[((long)(b * (NB + 1) + kb) * HH + row) * WW + col];
        float m2 = mask[((long)kb * HH + row) * WW + col];
        num += fabsf(xs[q] - y) * m2;
        den += m2;
    }
    block_reduce2(num, den, &g_acc[0], &g_acc[1]);
}

// ---------------- fused pan conv ----------------
__global__ void __launch_bounds__(256) k_pan_conv(const float* __restrict__ inp) {
    int b = blockIdx.y;
    int x0 = (blockIdx.x & 15) << 5, y0 = (blockIdx.x >> 4) << 5;
    __shared__ __align__(16) float s_in[72 * 76];
    __shared__ float s_mid[72 * 33];
    __shared__ float s_v[44];
    const float* src = inp + ((long)b * (NB + 1) + NB) * HWs;
    int t = threadIdx.x;
    if (t < 44) s_v[t] = (t < KS) ? g_v[t] : 0.f;
    for (int i = t; i < 72 * 72; i += 256) {
        int r = i / 72, c = i - r * 72;
        int gr = y0 + r - 20; gr = gr < 0 ? 0 : (gr > 511 ? 511 : gr);
        int gc = x0 + c - 20; gc = gc < 0 ? 0 : (gc > 511 ? 511 : gc);
        s_in[r * 76 + c] = src[gr * WW + gc];
    }
    __syncthreads();
    for (int i = t; i < 576; i += 256) {
        int r = i >> 3, cg = i & 7;
        const float4* row4 = reinterpret_cast<const float4*>(s_in + r * 76) + cg;
        float o0 = 0.f, o1 = 0.f, o2 = 0.f, o3 = 0.f;
        float4 cur = row4[0];
        #pragma unroll
        for (int tt = 0; tt < 10; ++tt) {
            float4 nxt = row4[tt + 1];
            float v0 = s_v[4*tt], v1 = s_v[4*tt+1], v2 = s_v[4*tt+2], v3 = s_v[4*tt+3];
            o0 += v0 * cur.x + v1 * cur.y + v2 * cur.z + v3 * cur.w;
            o1 += v0 * cur.y + v1 * cur.z + v2 * cur.w + v3 * nxt.x;
            o2 += v0 * cur.z + v1 * cur.w + v2 * nxt.x + v3 * nxt.y;
            o3 += v0 * cur.w + v1 * nxt.x + v2 * nxt.y + v3 * nxt.z;
            cur = nxt;
        }
        float v40 = s_v[40];
        o0 += v40 * cur.x; o1 += v40 * cur.y; o2 += v40 * cur.z; o3 += v40 * cur.w;
        float* dst = s_mid + r * 33 + 4 * cg;
        dst[0] = o0; dst[1] = o1; dst[2] = o2; dst[3] = o3;
    }
    __syncthreads();
    {
        int rg = t >> 5, c = t & 31, r0 = rg * 4;
        float o0 = 0.f, o1 = 0.f, o2 = 0.f, o3 = 0.f;
        #pragma unroll
        for (int m = 0; m < 44; ++m) {
            float x = s_mid[(r0 + m) * 33 + c];
            if (m <= 40) o0 += s_v[m] * x;
            if (m >= 1 && m <= 41) o1 += s_v[m - 1] * x;
            if (m >= 2 && m <= 42) o2 += s_v[m - 2] * x;
            if (m >= 3) o3 += s_v[m - 3] * x;
        }
        float* dst = g_panf + ((long)b << 18) + (long)(y0 + r0) * WW + x0 + c;
        dst[0] = o0; dst[WW] = o1; dst[2 * WW] = o2; dst[3 * WW] = o3;
    }
}

// ---------------- fused pan stats: dapf (w=8) + saapf, all sliding ----------------
__global__ void __launch_bounds__(256) k_pan_stats() {
    int b = blockIdx.y;
    int x0 = (blockIdx.x & 15) << 5, y0 = (blockIdx.x >> 4) << 5;
    __shared__ float s_pf[64][65];
    __shared__ float s_rs[64][49];
    __shared__ float s_da[48][49];
    __shared__ float s_q[48][33];
    const float* src = g_panf + ((long)b << 18);
    int t = threadIdx.x;
    for (int i = t; i < 64 * 64; i += 256) {
        int r = i >> 6, c = i & 63;
        int gr = y0 + r - 15, gc = x0 + c - 15;
        s_pf[r][c] = ((unsigned)gr < 512u && (unsigned)gc < 512u) ? src[gr * WW + gc] : 0.f;
    }
    __syncthreads();
    {
        int r = t >> 2, j0 = (t & 3) * 12;
        float s = 0.f;
        #pragma unroll
        for (int u = 1; u <= 16; ++u) s += s_pf[r][j0 + u];
        s_rs[r][j0] = s;
        #pragma unroll
        for (int j = 1; j < 12; ++j) {
            s += s_pf[r][j0 + j + 16] - s_pf[r][j0 + j];
            s_rs[r][j0 + j] = s;
        }
    }
    __syncthreads();
    if (t < 192) {
        int j = t >> 2, i0 = (t & 3) * 12;
        int gc = x0 + j - 7;
        bool cin = (unsigned)gc < 512u;
        float s = 0.f;
        #pragma unroll
        for (int u = 1; u <= 16; ++u) s += s_rs[i0 + u][j];
        {
            int gr = y0 + i0 - 7;
            bool in = cin && ((unsigned)gr < 512u);
            float d = in ? (s_pf[i0 + 8][j + 8] - s * (1.0f / 256.0f)) : 0.f;
            s_da[i0][j] = d;
            if (i0 >= 7 && i0 < 39 && j >= 7 && j < 39)
                g_dapf[((long)b << 18) + (long)gr * WW + gc] = d;
        }
        #pragma unroll
        for (int ii = 1; ii < 12; ++ii) {
            s += s_rs[i0 + ii + 16][j] - s_rs[i0 + ii][j];
            int gr = y0 + i0 + ii - 7;
            bool in = cin && ((unsigned)gr < 512u);
            float d = in ? (s_pf[i0 + ii + 8][j + 8] - s * (1.0f / 256.0f)) : 0.f;
            s_da[i0 + ii][j] = d;
            if (i0 + ii >= 7 && i0 + ii < 39 && j >= 7 && j < 39)
                g_dapf[((long)b << 18) + (long)gr * WW + gc] = d;
        }
    }
    __syncthreads();
    if (t < 192) {
        int r = t >> 2, w0 = (t & 3) * 8;
        float s = 0.f;
        #pragma unroll
        for (int u = 0; u < 16; ++u) { float x = s_da[r][w0 + u]; s += x * x; }
        s_q[r][w0] = s;
        #pragma unroll
        for (int w = 1; w < 8; ++w) {
            float x1 = s_da[r][w0 + w + 15], x0v = s_da[r][w0 + w - 1];
            s += x1 * x1 - x0v * x0v;
            s_q[r][w0 + w] = s;
        }
    }
    __syncthreads();
    {
        int ox = t & 31, r0 = (t >> 5) * 4;
        float s = 0.f;
        #pragma unroll
        for (int u = 0; u < 16; ++u) s += s_q[r0 + u][ox];
        float* dst = g_saapf + ((long)b << 18) + (long)(y0 + r0) * WW + x0 + ox;
        dst[0] = s;
        #pragma unroll
        for (int q = 1; q < 4; ++q) {
            s += s_q[r0 + q + 15][ox] - s_q[r0 + q - 1][ox];
            dst[q * WW] = s;
        }
    }
}

// ---------------- fused label-pan stats: dbpan (w=2) + sbbpan ----------------
__global__ void __launch_bounds__(256) k_lab_stats(const float* __restrict__ labels) {
    int b = blockIdx.y;
    int x0 = (blockIdx.x & 15) << 5, y0 = (blockIdx.x >> 4) << 5;
    __shared__ float s_lb[40][41];
    __shared__ float s_rs[40][37];
    __shared__ float s_db[36][37];
    __shared__ float s_q[36][33];
    const float* src = labels + ((long)b * (NB + 1) + NB) * HWs;
    int t = threadIdx.x;
    for (int i = t; i < 40 * 40; i += 256) {
        int r = i / 40, c = i - r * 40;
        int gr = y0 + r - 3, gc = x0 + c - 3;
        s_lb[r][c] = ((unsigned)gr < 512u && (unsigned)gc < 512u) ? src[gr * WW + gc] : 0.f;
    }
    __syncthreads();
    for (int i = t; i < 40 * 36; i += 256) {
        int r = i / 36, j = i - r * 36;
        float s = 0.f;
        #pragma unroll
        for (int u = 2; u <= 5; ++u) s += s_lb[r][j + u];
        s_rs[r][j] = s;
    }
    __syncthreads();
    for (int i = t; i < 36 * 36; i += 256) {
        int ii = i / 36, j = i - ii * 36;
        float s = 0.f;
        #pragma unroll
        for (int u = 1; u <= 4; ++u) s += s_rs[ii + u][j];
        int gr = y0 + ii - 1, gc = x0 + j - 1;
        bool in = ((unsigned)gr < 512u) && ((unsigned)gc < 512u);
        float d = in ? (s_lb[ii + 2][j + 2] - s * (1.0f / 16.0f)) : 0.f;
        s_db[ii][j] = d;
        if (ii >= 1 && ii < 33 && j >= 1 && j < 33)
            g_dbpan[((long)b << 18) + (long)gr * WW + gc] = d;
    }
    __syncthreads();
    for (int i = t; i < 36 * 32; i += 256) {
        int r = i >> 5, w = i & 31;
        float s = 0.f;
        #pragma unroll
        for (int u = 0; u < 4; ++u) { float x = s_db[r][w + u]; s += x * x; }
        s_q[r][w] = s;
    }
    __syncthreads();
    for (int i = t; i < 1024; i += 256) {
        int oy = i >> 5, ox = i & 31;
        float s = 0.f;
        #pragma unroll
        for (int u = 0; u < 4; ++u) s += s_q[oy + u][ox];
        g_sbbpan[((long)b << 18) + (long)(y0 + oy) * WW + x0 + ox] = s;
    }
}

// ---------------- fused structural: one block per (batch, tile), loop over 8 bands ----------------
// dynamic smem layout (floats):
//   B      [0, 9648)      scratch (thr: s_in 64x65, s_rs 64x49, s_db 48x49; final: s_out.., overlays)
//   s_pf   [9648, 12000)  48x49 dapf tile (persistent)
//   s_dbp  [12000, 13332) 36x37 dbpan tile (persistent)
//   s_saa  [13332, 14356) 32x32
//   s_sbb  [14356, 15380) 32x32
//   s_thr  [15380, 16404) 32x32
#define KSTRUCT_SMEM (16404 * 4)
__global__ void __launch_bounds__(256) k_struct(const float* __restrict__ inp, const float* __restrict__ outp) {
    extern __shared__ float S[];
    float* B     = S;
    float* s_pf  = S + 9648;
    float* s_dbp = S + 12000;
    float* s_saa = S + 13332;
    float* s_sbb = S + 14356;
    float* s_thr = S + 15380;
    int b = blockIdx.y;
    int x0 = (blockIdx.x & 15) << 5, y0 = (blockIdx.x >> 4) << 5;
    int t = threadIdx.x;

    // persistent per-(batch,tile) loads
    {
        const float* pfsrc = g_dapf + ((long)b << 18);
        for (int i = t; i < 48 * 48; i += 256) {
            int r = i / 48, c = i - r * 48;
            int gr = y0 + r - 7, gc = x0 + c - 7;
            s_pf[r * 49 + c] = ((unsigned)gr < 512u && (unsigned)gc < 512u) ? pfsrc[gr * WW + gc] : 0.f;
        }
        const float* dbsrc = g_dbpan + ((long)b << 18);
        for (int i = t; i < 36 * 36; i += 256) {
            int r = i / 36, c = i - r * 36;
            int gr = y0 + r - 1, gc = x0 + c - 1;
            s_dbp[r * 37 + c] = ((unsigned)gr < 512u && (unsigned)gc < 512u) ? dbsrc[gr * WW + gc] : 0.f;
        }
        const float* saab = g_saapf + ((long)b << 18);
        const float* sbbb = g_sbbpan + ((long)b << 18);
        for (int i = t; i < 1024; i += 256) {
            int oy = i >> 5, ox = i & 31;
            s_saa[i] = saab[(long)(y0 + oy) * WW + x0 + ox];
            s_sbb[i] = sbbb[(long)(y0 + oy) * WW + x0 + ox];
        }
    }

    float acc = 0.f;
    for (int kb = 0; kb < NB; ++kb) {
        __syncthreads();   // protect B reuse (and persistent loads on iter 0)
        // ===== thr part =====
        float* s_in = B;             // 64 x 65
        float* s_rs = B + 4160;      // 64 x 49
        float* s_db = B + 7296;      // 48 x 49
        const float* src = inp + ((long)b * (NB + 1) + kb) * HWs;
        for (int i = t; i < 64 * 64; i += 256) {
            int r = i >> 6, c = i & 63;
            int gr = y0 + r - 15, gc = x0 + c - 15;
            s_in[r * 65 + c] = ((unsigned)gr < 512u && (unsigned)gc < 512u) ? src[gr * WW + gc] : 0.f;
        }
        __syncthreads();
        {
            int r = t >> 2, j0 = (t & 3) * 12;
            const float* row = s_in + r * 65;
            float s = 0.f;
            #pragma unroll
            for (int u = 1; u <= 16; ++u) s += row[j0 + u];
            s_rs[r * 49 + j0] = s;
            #pragma unroll
            for (int j = 1; j < 12; ++j) {
                s += row[j0 + j + 16] - row[j0 + j];
                s_rs[r * 49 + j0 + j] = s;
            }
        }
        __syncthreads();
        if (t < 192) {
            int j = t >> 2, i0 = (t & 3) * 12;
            int gc = x0 + j - 7;
            bool cin = (unsigned)gc < 512u;
            float s = 0.f;
            #pragma unroll
            for (int u = 1; u <= 16; ++u) s += s_rs[(i0 + u) * 49 + j];
            {
                int gr = y0 + i0 - 7;
                bool in = cin && ((unsigned)gr < 512u);
                s_db[i0 * 49 + j] = in ? (s_in[(i0 + 8) * 65 + j + 8] - s * (1.0f / 256.0f)) : 0.f;
            }
            #pragma unroll
            for (int ii = 1; ii < 12; ++ii) {
                s += s_rs[(i0 + ii + 16) * 49 + j] - s_rs[(i0 + ii) * 49 + j];
                int gr = y0 + i0 + ii - 7;
                bool in = cin && ((unsigned)gr < 512u);
                s_db[(i0 + ii) * 49 + j] = in ? (s_in[(i0 + ii + 8) * 65 + j + 8] - s * (1.0f / 256.0f)) : 0.f;
            }
        }
        __syncthreads();
        float* s_e = B;              // 48 x 33 (overlays s_in, done)
        float* s_f = B + 1584;       // 48 x 33
        if (t < 192) {
            int r = t >> 2, w0 = (t & 3) * 8;
            const float* dbr = s_db + r * 49;
            const float* pfr = s_pf + r * 49;
            float se = 0.f, sf = 0.f;
            #pragma unroll
            for (int u = 0; u < 16; ++u) {
                float d = dbr[w0 + u], p = pfr[w0 + u];
                se += d * p; sf += d * d;
            }
            s_e[r * 33 + w0] = se; s_f[r * 33 + w0] = sf;
            #pragma unroll
            for (int w = 1; w < 8; ++w) {
                float d1 = dbr[w0 + w + 15], p1 = pfr[w0 + w + 15];
                float d0 = dbr[w0 + w - 1],  p0 = pfr[w0 + w - 1];
                se += d1 * p1 - d0 * p0;
                sf += d1 * d1 - d0 * d0;
                s_e[r * 33 + w0 + w] = se; s_f[r * 33 + w0 + w] = sf;
            }
        }
        __syncthreads();
        {
            int ox = t & 31, r0 = (t >> 5) * 4;
            float sab = 0.f, sbb = 0.f;
            #pragma unroll
            for (int u = 0; u < 16; ++u) {
                sab += s_e[(r0 + u) * 33 + ox];
                sbb += s_f[(r0 + u) * 33 + ox];
            }
            {
                float saa = s_saa[r0 * 32 + ox];
                s_thr[r0 * 32 + ox] = 1.f - sab / (sqrtf(saa * sbb) + EPSF);
            }
            #pragma unroll
            for (int q = 1; q < 4; ++q) {
                sab += s_e[(r0 + q + 15) * 33 + ox] - s_e[(r0 + q - 1) * 33 + ox];
                sbb += s_f[(r0 + q + 15) * 33 + ox] - s_f[(r0 + q - 1) * 33 + ox];
                float saa = s_saa[(r0 + q) * 32 + ox];
                s_thr[(r0 + q) * 32 + ox] = 1.f - sab / (sqrtf(saa * sbb) + EPSF);
            }
        }
        __syncthreads();
        // ===== final part =====
        float* s_out = B;            // 40 x 41
        float* s_rs2 = B + 1640;     // 40 x 37
        float* s_da  = B + 3120;     // 36 x 37
        float* s_e2  = B + 4452;     // 36 x 33
        float* s_f2  = B + 5640;     // 36 x 33
        const float* osrc = outp + ((long)(b * NB + kb)) * HWs;
        for (int i = t; i < 40 * 40; i += 256) {
            int r = i / 40, c = i - r * 40;
            int gr = y0 + r - 3, gc = x0 + c - 3;
            s_out[r * 41 + c] = ((unsigned)gr < 512u && (unsigned)gc < 512u) ? osrc[gr * WW + gc] : 0.f;
        }
        __syncthreads();
        for (int i = t; i < 40 * 36; i += 256) {
            int r = i / 36, j = i - r * 36;
            float s = 0.f;
            #pragma unroll
            for (int u = 2; u <= 5; ++u) s += s_out[r * 41 + j + u];
            s_rs2[r * 37 + j] = s;
        }
        __syncthreads();
        for (int i = t; i < 36 * 36; i += 256) {
            int ii = i / 36, j = i - ii * 36;
            float s = 0.f;
            #pragma unroll
            for (int u = 1; u <= 4; ++u) s += s_rs2[(ii + u) * 37 + j];
            int gr = y0 + ii - 1, gc = x0 + j - 1;
            bool in = ((unsigned)gr < 512u) && ((unsigned)gc < 512u);
            s_da[ii * 37 + j] = in ? (s_out[(ii + 2) * 41 + j + 2] - s * (1.0f / 16.0f)) : 0.f;
        }
        __syncthreads();
        for (int i = t; i < 36 * 32; i += 256) {
            int r = i >> 5, w = i & 31;
            float se = 0.f, sf = 0.f;
            #pragma unroll
            for (int u = 0; u < 4; ++u) {
                float A = s_da[r * 37 + w + u], Bv = s_dbp[r * 37 + w + u];
                se += A * Bv; sf += A * A;
            }
            s_e2[r * 33 + w] = se; s_f2[r * 33 + w] = sf;
        }
        __syncthreads();
        {
            int ox = t & 31, r0 = (t >> 5) * 4;
            float sab = 0.f, saa = 0.f;
            #pragma unroll
            for (int u = 0; u < 4; ++u) {
                sab += s_e2[(r0 + u) * 33 + ox];
                saa += s_f2[(r0 + u) * 33 + ox];
            }
            #pragma unroll
            for (int q = 0; q < 4; ++q) {
                if (q > 0) {
                    sab += s_e2[(r0 + q + 3) * 33 + ox] - s_e2[(r0 + q - 1) * 33 + ox];
                    saa += s_f2[(r0 + q + 3) * 33 + ox] - s_f2[(r0 + q - 1) * 33 + ox];
                }
                float sbb = s_sbb[(r0 + q) * 32 + ox];
                float xc = sab / (sqrtf(saa * sbb) + EPSF);
                xc = fmaxf(xc, -1.f);
                float X = 1.f - xc;
                float thr = s_thr[(r0 + q) * 32 + ox];
                acc += (X > thr) ? X : 0.f;
            }
        }
    }
    block_reduce1(acc, &g_acc[2]);
}

__global__ void k_out(float* __restrict__ out) {
    if (threadIdx.x == 0) {
        double lspec = g_acc[0] / g_acc[1];
        double lstruct = g_acc[2] / (double)((long)BB * NB * HWs);
        out[0] = (float)(lspec + BETAD * lstruct);
    }
}

// ---------------- launch ----------------
extern "C" void kernel_launch(void* const* d_in, const int* in_sizes, int n_in,
                              void* d_out, int out_size) {
    const float* outputs = (const float*)d_in[0];
    const float* labels  = (const float*)d_in[1];
    const float* inp     = (const float*)d_in[2];
    const float* mtf     = (const float*)d_in[3];
    const float* mask    = (const float*)d_in[4];
    float* out = (float*)d_out;

    cudaFuncSetAttribute(k_struct, cudaFuncAttributeMaxDynamicSharedMemorySize, KSTRUCT_SMEM);

    k_setup<<<2, 256>>>(mtf);
    k_spec_h<<<BB * NB * 256, 256>>>(outputs);
    k_spec_v<<<dim3(16, BB * NB), 256>>>(labels, mask);
    k_pan_conv<<<dim3(256, BB), 256>>>(inp);
    k_pan_stats<<<dim3(256, BB), 256>>>();
    k_lab_stats<<<dim3(256, BB), 256>>>(labels);
    k_struct<<<dim3(256, BB), 256, KSTRUCT_SMEM>>>(inp, outputs);
    k_out<<<1, 32>>>(out);
    (void)in_sizes; (void)n_in; (void)out_size;
}

// round 12
// speedup vs baseline: 1.1805x; 1.1805x over previous
#include <cuda_runtime.h>

#define BB 4
#define NB 8
#define HH 512
#define WW 512
#define HWs (HH*WW)
#define KS 41
#define KR 20
#define SS 128
#define EPSF 1e-20f
#define BETAD 0.25

// ---------------- device scratch ----------------
__device__ float g_v[NB*KS];
__device__ float g_sp[BB*NB*HH*SS];
__device__ float g_panf[BB*HWs];
__device__ float g_dapf[BB*HWs];
__device__ float g_saapf[BB*HWs];
__device__ float g_dbpan[BB*HWs];
__device__ float g_sbbpan[BB*HWs];
__device__ double g_acc[3];

// ---------------- reduction helpers ----------------
__device__ __forceinline__ void block_reduce2(float a, float b, double* d0, double* d1) {
    #pragma unroll
    for (int o = 16; o; o >>= 1) {
        a += __shfl_down_sync(0xffffffffu, a, o);
        b += __shfl_down_sync(0xffffffffu, b, o);
    }
    __shared__ float sa[8], sb[8];
    int lane = threadIdx.x & 31, wid = threadIdx.x >> 5;
    if (lane == 0) { sa[wid] = a; sb[wid] = b; }
    __syncthreads();
    if (wid == 0) {
        int nw = blockDim.x >> 5;
        a = (lane < nw) ? sa[lane] : 0.f;
        b = (lane < nw) ? sb[lane] : 0.f;
        #pragma unroll
        for (int o = 4; o; o >>= 1) {
            a += __shfl_down_sync(0xffffffffu, a, o);
            b += __shfl_down_sync(0xffffffffu, b, o);
        }
        if (lane == 0) { atomicAdd(d0, (double)a); atomicAdd(d1, (double)b); }
    }
}

__device__ __forceinline__ void block_reduce1(float a, double* d0) {
    #pragma unroll
    for (int o = 16; o; o >>= 1) a += __shfl_down_sync(0xffffffffu, a, o);
    __shared__ float sa[8];
    int lane = threadIdx.x & 31, wid = threadIdx.x >> 5;
    if (lane == 0) sa[wid] = a;
    __syncthreads();
    if (wid == 0) {
        int nw = blockDim.x >> 5;
        a = (lane < nw) ? sa[lane] : 0.f;
        #pragma unroll
        for (int o = 4; o; o >>= 1) a += __shfl_down_sync(0xffffffffu, a, o);
        if (lane == 0) atomicAdd(d0, (double)a);
    }
}

// ---------------- setup ----------------
__global__ void k_setup(const float* __restrict__ mtf) {
    int t = blockIdx.x * blockDim.x + threadIdx.x;
    if (t < NB * KS) {
        int k = t / KS, i = t - k * KS;
        g_v[t] = mtf[k * KS * KS + i * KS + KR] / sqrtf(mtf[k * KS * KS + KR * KS + KR]);
    }
    if (t < 3) g_acc[t] = 0.0;
}

// ---------------- L_spec horizontal conv: float4 rolling window ----------------
__global__ void __launch_bounds__(256) k_spec_h(const float* __restrict__ outp) {
    int hp = blockIdx.x & 255;
    int bk = blockIdx.x >> 8;
    int k  = bk & 7;
    __shared__ __align__(16) float s_row[2][556];
    __shared__ float s_v[44];
    int t = threadIdx.x;
    if (t < 44) s_v[t] = (t < KS) ? g_v[k * KS + t] : 0.f;
    if (t < 88) { int r = t / 44, p = t % 44; s_row[r][p < 22 ? p : p - 22 + 534] = 0.f; }
    const float* src = outp + (long)bk * HWs + (long)(2 * hp) * WW;
    for (int i = t; i < 1024; i += 256) {
        int r = i >> 9, c = i & 511;
        s_row[r][22 + c] = src[r * WW + c];
    }
    __syncthreads();
    int r = t >> 7, jj = t & 127;
    const float4* row4 = reinterpret_cast<const float4*>(s_row[r]) + (jj + 1);
    float4 cur = row4[0];
    float s = 0.f;
    #pragma unroll
    for (int tt = 0; tt < 10; ++tt) {
        float4 nxt = row4[tt + 1];
        s += s_v[4*tt] * cur.x + s_v[4*tt+1] * cur.y + s_v[4*tt+2] * cur.z + s_v[4*tt+3] * cur.w;
        cur = nxt;
    }
    s += s_v[40] * cur.x;
    g_sp[((long)bk * HH + 2 * hp + r) * SS + jj] = s;
}

// ---------------- L_spec vertical: smem tile, 4 outputs/thread ----------------
__global__ void __launch_bounds__(256) k_spec_v(const float* __restrict__ labels, const float* __restrict__ mask) {
    int bk = blockIdx.y;
    int kb = bk & 7, b = bk >> 3;
    int ii0 = blockIdx.x * 8;
    __shared__ float s_sp[69][128];
    __shared__ float s_v[KS];
    int t = threadIdx.x;
    if (t < KS) s_v[t] = g_v[kb * KS + t];
    const float* spb = g_sp + (long)bk * HH * SS;
    for (int i = t; i < 69 * 128; i += 256) {
        int m = i >> 7, jj = i & 127;
        int gr = 4 * ii0 - 18 + m;
        s_sp[m][jj] = ((unsigned)gr < 512u) ? spb[(long)gr * SS + jj] : 0.f;
    }
    __syncthreads();
    int jj = t & 127, half = t >> 7;
    int base = 16 * half;
    float o0 = 0.f, o1 = 0.f, o2 = 0.f, o3 = 0.f;
    #pragma unroll
    for (int m = 0; m < 53; ++m) {
        float x = s_sp[base + m][jj];
        if (m <= 40) o0 += s_v[m] * x;
        if (m >= 4 && m <= 44) o1 += s_v[m - 4] * x;
        if (m >= 8 && m <= 48) o2 += s_v[m - 8] * x;
        if (m >= 12) o3 += s_v[m - 12] * x;
    }
    float xs[4] = {o0, o1, o2, o3};
    float num = 0.f, den = 0.f;
    #pragma unroll
    for (int q = 0; q < 4; ++q) {
        int ii = ii0 + 4 * half + q;
        int row = 2 + 4 * ii, col = 2 + 4 * jj;
        float y = labels[((long)(b * (NB + 1) + kb) * HH + row) * WW + col];
        float m2 = mask[((long)kb * HH + row) * WW + col];
        num += fabsf(xs[q] - y) * m2;
        den += m2;
    }
    block_reduce2(num, den, &g_acc[0], &g_acc[1]);
}

// ---------------- fused pan conv ----------------
__global__ void __launch_bounds__(256) k_pan_conv(const float* __restrict__ inp) {
    int b = blockIdx.y;
    int x0 = (blockIdx.x & 15) << 5, y0 = (blockIdx.x >> 4) << 5;
    __shared__ __align__(16) float s_in[72 * 76];
    __shared__ float s_mid[72 * 33];
    __shared__ float s_v[44];
    const float* src = inp + ((long)b * (NB + 1) + NB) * HWs;
    int t = threadIdx.x;
    if (t < 44) s_v[t] = (t < KS) ? g_v[t] : 0.f;
    for (int i = t; i < 72 * 72; i += 256) {
        int r = i / 72, c = i - r * 72;
        int gr = y0 + r - 20; gr = gr < 0 ? 0 : (gr > 511 ? 511 : gr);
        int gc = x0 + c - 20; gc = gc < 0 ? 0 : (gc > 511 ? 511 : gc);
        s_in[r * 76 + c] = src[gr * WW + gc];
    }
    __syncthreads();
    for (int i = t; i < 576; i += 256) {
        int r = i >> 3, cg = i & 7;
        const float4* row4 = reinterpret_cast<const float4*>(s_in + r * 76) + cg;
        float o0 = 0.f, o1 = 0.f, o2 = 0.f, o3 = 0.f;
        float4 cur = row4[0];
        #pragma unroll
        for (int tt = 0; tt < 10; ++tt) {
            float4 nxt = row4[tt + 1];
            float v0 = s_v[4*tt], v1 = s_v[4*tt+1], v2 = s_v[4*tt+2], v3 = s_v[4*tt+3];
            o0 += v0 * cur.x + v1 * cur.y + v2 * cur.z + v3 * cur.w;
            o1 += v0 * cur.y + v1 * cur.z + v2 * cur.w + v3 * nxt.x;
            o2 += v0 * cur.z + v1 * cur.w + v2 * nxt.x + v3 * nxt.y;
            o3 += v0 * cur.w + v1 * nxt.x + v2 * nxt.y + v3 * nxt.z;
            cur = nxt;
        }
        float v40 = s_v[40];
        o0 += v40 * cur.x; o1 += v40 * cur.y; o2 += v40 * cur.z; o3 += v40 * cur.w;
        float* dst = s_mid + r * 33 + 4 * cg;
        dst[0] = o0; dst[1] = o1; dst[2] = o2; dst[3] = o3;
    }
    __syncthreads();
    {
        int rg = t >> 5, c = t & 31, r0 = rg * 4;
        float o0 = 0.f, o1 = 0.f, o2 = 0.f, o3 = 0.f;
        #pragma unroll
        for (int m = 0; m < 44; ++m) {
            float x = s_mid[(r0 + m) * 33 + c];
            if (m <= 40) o0 += s_v[m] * x;
            if (m >= 1 && m <= 41) o1 += s_v[m - 1] * x;
            if (m >= 2 && m <= 42) o2 += s_v[m - 2] * x;
            if (m >= 3) o3 += s_v[m - 3] * x;
        }
        float* dst = g_panf + ((long)b << 18) + (long)(y0 + r0) * WW + x0 + c;
        dst[0] = o0; dst[WW] = o1; dst[2 * WW] = o2; dst[3 * WW] = o3;
    }
}

// ---------------- fused pan stats: dapf (w=8) + saapf, all sliding ----------------
__global__ void __launch_bounds__(256) k_pan_stats() {
    int b = blockIdx.y;
    int x0 = (blockIdx.x & 15) << 5, y0 = (blockIdx.x >> 4) << 5;
    __shared__ float s_pf[64][65];
    __shared__ float s_rs[64][49];
    __shared__ float s_da[48][49];
    __shared__ float s_q[48][33];
    const float* src = g_panf + ((long)b << 18);
    int t = threadIdx.x;
    for (int i = t; i < 64 * 64; i += 256) {
        int r = i >> 6, c = i & 63;
        int gr = y0 + r - 15, gc = x0 + c - 15;
        s_pf[r][c] = ((unsigned)gr < 512u && (unsigned)gc < 512u) ? src[gr * WW + gc] : 0.f;
    }
    __syncthreads();
    {
        int r = t >> 2, j0 = (t & 3) * 12;
        float s = 0.f;
        #pragma unroll
        for (int u = 1; u <= 16; ++u) s += s_pf[r][j0 + u];
        s_rs[r][j0] = s;
        #pragma unroll
        for (int j = 1; j < 12; ++j) {
            s += s_pf[r][j0 + j + 16] - s_pf[r][j0 + j];
            s_rs[r][j0 + j] = s;
        }
    }
    __syncthreads();
    if (t < 192) {
        int j = t >> 2, i0 = (t & 3) * 12;
        int gc = x0 + j - 7;
        bool cin = (unsigned)gc < 512u;
        float s = 0.f;
        #pragma unroll
        for (int u = 1; u <= 16; ++u) s += s_rs[i0 + u][j];
        {
            int gr = y0 + i0 - 7;
            bool in = cin && ((unsigned)gr < 512u);
            float d = in ? (s_pf[i0 + 8][j + 8] - s * (1.0f / 256.0f)) : 0.f;
            s_da[i0][j] = d;
            if (i0 >= 7 && i0 < 39 && j >= 7 && j < 39)
                g_dapf[((long)b << 18) + (long)gr * WW + gc] = d;
        }
        #pragma unroll
        for (int ii = 1; ii < 12; ++ii) {
            s += s_rs[i0 + ii + 16][j] - s_rs[i0 + ii][j];
            int gr = y0 + i0 + ii - 7;
            bool in = cin && ((unsigned)gr < 512u);
            float d = in ? (s_pf[i0 + ii + 8][j + 8] - s * (1.0f / 256.0f)) : 0.f;
            s_da[i0 + ii][j] = d;
            if (i0 + ii >= 7 && i0 + ii < 39 && j >= 7 && j < 39)
                g_dapf[((long)b << 18) + (long)gr * WW + gc] = d;
        }
    }
    __syncthreads();
    if (t < 192) {
        int r = t >> 2, w0 = (t & 3) * 8;
        float s = 0.f;
        #pragma unroll
        for (int u = 0; u < 16; ++u) { float x = s_da[r][w0 + u]; s += x * x; }
        s_q[r][w0] = s;
        #pragma unroll
        for (int w = 1; w < 8; ++w) {
            float x1 = s_da[r][w0 + w + 15], x0v = s_da[r][w0 + w - 1];
            s += x1 * x1 - x0v * x0v;
            s_q[r][w0 + w] = s;
        }
    }
    __syncthreads();
    {
        int ox = t & 31, r0 = (t >> 5) * 4;
        float s = 0.f;
        #pragma unroll
        for (int u = 0; u < 16; ++u) s += s_q[r0 + u][ox];
        float* dst = g_saapf + ((long)b << 18) + (long)(y0 + r0) * WW + x0 + ox;
        dst[0] = s;
        #pragma unroll
        for (int q = 1; q < 4; ++q) {
            s += s_q[r0 + q + 15][ox] - s_q[r0 + q - 1][ox];
            dst[q * WW] = s;
        }
    }
}

// ---------------- fused label-pan stats: dbpan (w=2) + sbbpan ----------------
__global__ void __launch_bounds__(256) k_lab_stats(const float* __restrict__ labels) {
    int b = blockIdx.y;
    int x0 = (blockIdx.x & 15) << 5, y0 = (blockIdx.x >> 4) << 5;
    __shared__ float s_lb[40][41];
    __shared__ float s_rs[40][37];
    __shared__ float s_db[36][37];
    __shared__ float s_q[36][33];
    const float* src = labels + ((long)b * (NB + 1) + NB) * HWs;
    int t = threadIdx.x;
    for (int i = t; i < 40 * 40; i += 256) {
        int r = i / 40, c = i - r * 40;
        int gr = y0 + r - 3, gc = x0 + c - 3;
        s_lb[r][c] = ((unsigned)gr < 512u && (unsigned)gc < 512u) ? src[gr * WW + gc] : 0.f;
    }
    __syncthreads();
    for (int i = t; i < 40 * 36; i += 256) {
        int r = i / 36, j = i - r * 36;
        float s = 0.f;
        #pragma unroll
        for (int u = 2; u <= 5; ++u) s += s_lb[r][j + u];
        s_rs[r][j] = s;
    }
    __syncthreads();
    for (int i = t; i < 36 * 36; i += 256) {
        int ii = i / 36, j = i - ii * 36;
        float s = 0.f;
        #pragma unroll
        for (int u = 1; u <= 4; ++u) s += s_rs[ii + u][j];
        int gr = y0 + ii - 1, gc = x0 + j - 1;
        bool in = ((unsigned)gr < 512u) && ((unsigned)gc < 512u);
        float d = in ? (s_lb[ii + 2][j + 2] - s * (1.0f / 16.0f)) : 0.f;
        s_db[ii][j] = d;
        if (ii >= 1 && ii < 33 && j >= 1 && j < 33)
            g_dbpan[((long)b << 18) + (long)gr * WW + gc] = d;
    }
    __syncthreads();
    for (int i = t; i < 36 * 32; i += 256) {
        int r = i >> 5, w = i & 31;
        float s = 0.f;
        #pragma unroll
        for (int u = 0; u < 4; ++u) { float x = s_db[r][w + u]; s += x * x; }
        s_q[r][w] = s;
    }
    __syncthreads();
    for (int i = t; i < 1024; i += 256) {
        int oy = i >> 5, ox = i & 31;
        float s = 0.f;
        #pragma unroll
        for (int u = 0; u < 4; ++u) s += s_q[oy + u][ox];
        g_sbbpan[((long)b << 18) + (long)(y0 + oy) * WW + x0 + ox] = s;
    }
}

// ---------------- fused structural: thr + final (R8 proven shape) ----------------
__global__ void __launch_bounds__(256) k_struct(const float* __restrict__ inp, const float* __restrict__ outp) {
    int img = blockIdx.y;
    int b = img >> 3, kb = img & 7;
    int x0 = (blockIdx.x & 15) << 5, y0 = (blockIdx.x >> 4) << 5;
    __shared__ float B[10672];
    float* s_thr = B + 9648;
    int t = threadIdx.x;
    {
        float* s_in = B;
        float* s_rs = B + 4160;
        float* s_db = B + 7296;
        const float* src = inp + ((long)b * (NB + 1) + kb) * HWs;
        for (int i = t; i < 64 * 64; i += 256) {
            int r = i >> 6, c = i & 63;
            int gr = y0 + r - 15, gc = x0 + c - 15;
            s_in[r * 65 + c] = ((unsigned)gr < 512u && (unsigned)gc < 512u) ? src[gr * WW + gc] : 0.f;
        }
        __syncthreads();
        {
            int r = t >> 2, j0 = (t & 3) * 12;
            const float* row = s_in + r * 65;
            float s = 0.f;
            #pragma unroll
            for (int u = 1; u <= 16; ++u) s += row[j0 + u];
            s_rs[r * 49 + j0] = s;
            #pragma unroll
            for (int j = 1; j < 12; ++j) {
                s += row[j0 + j + 16] - row[j0 + j];
                s_rs[r * 49 + j0 + j] = s;
            }
        }
        __syncthreads();
        if (t < 192) {
            int j = t >> 2, i0 = (t & 3) * 12;
            int gc = x0 + j - 7;
            bool cin = (unsigned)gc < 512u;
            float s = 0.f;
            #pragma unroll
            for (int u = 1; u <= 16; ++u) s += s_rs[(i0 + u) * 49 + j];
            {
                int gr = y0 + i0 - 7;
                bool in = cin && ((unsigned)gr < 512u);
                s_db[i0 * 49 + j] = in ? (s_in[(i0 + 8) * 65 + j + 8] - s * (1.0f / 256.0f)) : 0.f;
            }
            #pragma unroll
            for (int ii = 1; ii < 12; ++ii) {
                s += s_rs[(i0 + ii + 16) * 49 + j] - s_rs[(i0 + ii) * 49 + j];
                int gr = y0 + i0 + ii - 7;
                bool in = cin && ((unsigned)gr < 512u);
                s_db[(i0 + ii) * 49 + j] = in ? (s_in[(i0 + ii + 8) * 65 + j + 8] - s * (1.0f / 256.0f)) : 0.f;
            }
        }
        __syncthreads();
        float* s_pf = B;
        float* s_e  = B + 2352;
        float* s_f  = B + 3936;
        const float* pfsrc = g_dapf + ((long)b << 18);
        for (int i = t; i < 48 * 48; i += 256) {
            int r = i / 48, c = i - r * 48;
            int gr = y0 + r - 7, gc = x0 + c - 7;
            s_pf[r * 49 + c] = ((unsigned)gr < 512u && (unsigned)gc < 512u) ? pfsrc[gr * WW + gc] : 0.f;
        }
        __syncthreads();
        if (t < 192) {
            int r = t >> 2, w0 = (t & 3) * 8;
            const float* dbr = s_db + r * 49;
            const float* pfr = s_pf + r * 49;
            float se = 0.f, sf = 0.f;
            #pragma unroll
            for (int u = 0; u < 16; ++u) {
                float d = dbr[w0 + u], p = pfr[w0 + u];
                se += d * p; sf += d * d;
            }
            s_e[r * 33 + w0] = se; s_f[r * 33 + w0] = sf;
            #pragma unroll
            for (int w = 1; w < 8; ++w) {
                float d1 = dbr[w0 + w + 15], p1 = pfr[w0 + w + 15];
                float d0 = dbr[w0 + w - 1],  p0 = pfr[w0 + w - 1];
                se += d1 * p1 - d0 * p0;
                sf += d1 * d1 - d0 * d0;
                s_e[r * 33 + w0 + w] = se; s_f[r * 33 + w0 + w] = sf;
            }
        }
        __syncthreads();
        {
            int ox = t & 31, r0 = (t >> 5) * 4;
            const float* saab = g_saapf + ((long)b << 18);
            float sab = 0.f, sbb = 0.f;
            #pragma unroll
            for (int u = 0; u < 16; ++u) {
                sab += s_e[(r0 + u) * 33 + ox];
                sbb += s_f[(r0 + u) * 33 + ox];
            }
            {
                float saa = saab[(long)(y0 + r0) * WW + x0 + ox];
                s_thr[r0 * 32 + ox] = 1.f - sab / (sqrtf(saa * sbb) + EPSF);
            }
            #pragma unroll
            for (int q = 1; q < 4; ++q) {
                sab += s_e[(r0 + q + 15) * 33 + ox] - s_e[(r0 + q - 1) * 33 + ox];
                sbb += s_f[(r0 + q + 15) * 33 + ox] - s_f[(r0 + q - 1) * 33 + ox];
                float saa = saab[(long)(y0 + r0 + q) * WW + x0 + ox];
                s_thr[(r0 + q) * 32 + ox] = 1.f - sab / (sqrtf(saa * sbb) + EPSF);
            }
        }
    }
    __syncthreads();
    {
        float* s_out = B;
        float* s_rs2 = B + 1640;
        float* s_da  = B + 3120;
        float* s_dbp = B + 4452;
        float* s_e2  = B + 5784;
        float* s_f2  = B + 6972;
        const float* src = outp + (long)img * HWs;
        for (int i = t; i < 40 * 40; i += 256) {
            int r = i / 40, c = i - r * 40;
            int gr = y0 + r - 3, gc = x0 + c - 3;
            s_out[r * 41 + c] = ((unsigned)gr < 512u && (unsigned)gc < 512u) ? src[gr * WW + gc] : 0.f;
        }
        const float* dbsrc = g_dbpan + ((long)b << 18);
        for (int i = t; i < 36 * 36; i += 256) {
            int r = i / 36, c = i - r * 36;
            int gr = y0 + r - 1, gc = x0 + c - 1;
            s_dbp[r * 37 + c] = ((unsigned)gr < 512u && (unsigned)gc < 512u) ? dbsrc[gr * WW + gc] : 0.f;
        }
        __syncthreads();
        for (int i = t; i < 40 * 36; i += 256) {
            int r = i / 36, j = i - r * 36;
            float s = 0.f;
            #pragma unroll
            for (int u = 2; u <= 5; ++u) s += s_out[r * 41 + j + u];
            s_rs2[r * 37 + j] = s;
        }
        __syncthreads();
        for (int i = t; i < 36 * 36; i += 256) {
            int ii = i / 36, j = i - ii * 36;
            float s = 0.f;
            #pragma unroll
            for (int u = 1; u <= 4; ++u) s += s_rs2[(ii + u) * 37 + j];
            int gr = y0 + ii - 1, gc = x0 + j - 1;
            bool in = ((unsigned)gr < 512u) && ((unsigned)gc < 512u);
            s_da[ii * 37 + j] = in ? (s_out[(ii + 2) * 41 + j + 2] - s * (1.0f / 16.0f)) : 0.f;
        }
        __syncthreads();
        for (int i = t; i < 36 * 32; i += 256) {
            int r = i >> 5, w = i & 31;
            float se = 0.f, sf = 0.f;
            #pragma unroll
            for (int u = 0; u < 4; ++u) {
                float A = s_da[r * 37 + w + u], Bv = s_dbp[r * 37 + w + u];
                se += A * Bv; sf += A * A;
            }
            s_e2[r * 33 + w] = se; s_f2[r * 33 + w] = sf;
        }
        __syncthreads();
        const float* sbbb = g_sbbpan + ((long)b << 18);
        float acc = 0.f;
        {
            int ox = t & 31, r0 = (t >> 5) * 4;
            float sab = 0.f, saa = 0.f;
            #pragma unroll
            for (int u = 0; u < 4; ++u) {
                sab += s_e2[(r0 + u) * 33 + ox];
                saa += s_f2[(r0 + u) * 33 + ox];
            }
            #pragma unroll
            for (int q = 0; q < 4; ++q) {
                if (q > 0) {
                    sab += s_e2[(r0 + q + 3) * 33 + ox] - s_e2[(r0 + q - 1) * 33 + ox];
                    saa += s_f2[(r0 + q + 3) * 33 + ox] - s_f2[(r0 + q - 1) * 33 + ox];
                }
                float sbb = sbbb[(long)(y0 + r0 + q) * WW + x0 + ox];
                float xc = sab / (sqrtf(saa * sbb) + EPSF);
                xc = fmaxf(xc, -1.f);
                float X = 1.f - xc;
                float thr = s_thr[(r0 + q) * 32 + ox];
                acc += (X > thr) ? X : 0.f;
            }
        }
        block_reduce1(acc, &g_acc[2]);
    }
}

__global__ void k_out(float* __restrict__ out) {
    if (threadIdx.x == 0) {
        double lspec = g_acc[0] / g_acc[1];
        double lstruct = g_acc[2] / (double)((long)BB * NB * HWs);
        out[0] = (float)(lspec + BETAD * lstruct);
    }
}

// ---------------- launch: fork independent chains onto side streams ----------------
extern "C" void kernel_launch(void* const* d_in, const int* in_sizes, int n_in,
                              void* d_out, int out_size) {
    const float* outputs = (const float*)d_in[0];
    const float* labels  = (const float*)d_in[1];
    const float* inp     = (const float*)d_in[2];
    const float* mtf     = (const float*)d_in[3];
    const float* mask    = (const float*)d_in[4];
    float* out = (float*)d_out;

    static cudaStream_t s1 = nullptr, s2 = nullptr;
    static cudaEvent_t evSetup = nullptr, evSpec = nullptr, evLab = nullptr;
    if (!s1) {
        cudaStreamCreateWithFlags(&s1, cudaStreamNonBlocking);
        cudaStreamCreateWithFlags(&s2, cudaStreamNonBlocking);
        cudaEventCreateWithFlags(&evSetup, cudaEventDisableTiming);
        cudaEventCreateWithFlags(&evSpec, cudaEventDisableTiming);
        cudaEventCreateWithFlags(&evLab, cudaEventDisableTiming);
    }

    k_setup<<<2, 256>>>(mtf);
    cudaEventRecord(evSetup, 0);

    // spec chain on s1
    cudaStreamWaitEvent(s1, evSetup, 0);
    k_spec_h<<<BB * NB * 256, 256, 0, s1>>>(outputs);
    k_spec_v<<<dim3(16, BB * NB), 256, 0, s1>>>(labels, mask);
    cudaEventRecord(evSpec, s1);

    // lab_stats on s2
    cudaStreamWaitEvent(s2, evSetup, 0);
    k_lab_stats<<<dim3(256, BB), 256, 0, s2>>>(labels);
    cudaEventRecord(evLab, s2);

    // pan chain + struct on main stream
    k_pan_conv<<<dim3(256, BB), 256>>>(inp);
    k_pan_stats<<<dim3(256, BB), 256>>>();
    cudaStreamWaitEvent(0, evLab, 0);
    k_struct<<<dim3(256, BB * NB), 256>>>(inp, outputs);

    cudaStreamWaitEvent(0, evSpec, 0);
    k_out<<<1, 32>>>(out);
    (void)in_sizes; (void)n_in; (void)out_size;
}